// round 14
// baseline (speedup 1.0000x reference)
#include <cuda_runtime.h>
#include <math.h>

#define NSENT 8192
#define C     1024
#define NCTA  64                  // producer CTAs per direction
#define NWARP 8                   // 8 compute warps, 2 columns each
#define NTHREADS 256
#define NCTA_TOTAL (2*NCTA)
#define FSTRIDE 8
#define ROWS_PER_CTA (NSENT / NCTA_TOTAL)   // 64

typedef unsigned long long u64;

// -------- device scratch (no allocations allowed) --------
__device__ __align__(16) float g_E [C*C];   // exp(T) row-major [k][j]  (beta)
__device__ __align__(16) float g_ET[C*C];   // transpose [j][k]         (alpha)
__device__ __align__(16) float g_beta[(size_t)NSENT*C];
// self-tagged q pairs, strong 8B: low32 = value bits, high32 = step tag
__device__ __align__(16) u64 g_pair[2][2][C];      // [dir][buf][class]
__device__ double   g_offA[NSENT];
__device__ double   g_offB[NSENT];
__device__ double   g_Zbase;
__device__ unsigned g_jflags[NCTA_TOTAL*FSTRIDE];

__device__ __forceinline__ unsigned ld_acq(const unsigned* p) {
    unsigned v;
    asm volatile("ld.acquire.gpu.global.u32 %0, [%1];" : "=r"(v) : "l"(p) : "memory");
    return v;
}
__device__ __forceinline__ void st_rel(unsigned* p, unsigned v) {
    asm volatile("st.release.gpu.global.u32 [%0], %1;" :: "l"(p), "r"(v) : "memory");
}
// morally strong 8B pair ops: aligned strong <=64b => single-copy atomic
__device__ __forceinline__ void st_pair_rel(u64* p, float val, unsigned tag) {
    u64 u = ((u64)tag << 32) | (u64)__float_as_uint(val);
    asm volatile("st.release.gpu.global.b64 [%0], %1;" :: "l"(p), "l"(u) : "memory");
}
__device__ __forceinline__ u64 ld_pair_acq(const u64* p) {
    u64 u;
    asm volatile("ld.acquire.gpu.global.b64 %0, [%1];" : "=l"(u) : "l"(p) : "memory");
    return u;
}
__device__ __forceinline__ u64 ld_pair_cg(const u64* p) {
    u64 u;
    asm volatile("ld.global.cg.b64 %0, [%1];" : "=l"(u) : "l"(p) : "memory");
    return u;
}
__device__ __forceinline__ float frcp(float x) {
    float r;
    asm("rcp.approx.f32 %0, %1;" : "=f"(r) : "f"(x));
    return r;
}

// -------- init kernel --------
__global__ void crf_init(const float* __restrict__ T) {
    int idx = blockIdx.x * blockDim.x + threadIdx.x;
    if (idx < C*C) {
        float e = expf(T[idx]);
        g_E[idx] = e;
        int k = idx / C, j = idx % C;
        g_ET[j*C + k] = e;
    }
    if (idx < 2*2*C) ((u64*)g_pair)[idx] = 0ull;
    if (idx < NCTA_TOTAL*FSTRIDE) g_jflags[idx] = 0u;
}

// -------- persistent forward+backward kernel --------
__global__ void __launch_bounds__(NTHREADS, 1) crf_main(const float* __restrict__ scores,
                                                        float* __restrict__ out) {
    const int  cta    = blockIdx.x;
    const bool isBeta = (cta >= NCTA);
    const int  dir    = isBeta ? 1 : 0;
    const int  grp    = isBeta ? (cta - NCTA) : cta;
    const int  warp   = threadIdx.x >> 5;
    const int  lane   = threadIdx.x & 31;
    const int  j0     = grp * 16 + warp * 2;   // 2 columns per warp

    __shared__ __align__(16) float q_sm[2][C];     // double-buffered q vector
    __shared__ float redsum[NWARP];
    __shared__ float k_sm[ROWS_PER_CTA];

    // E coefficients for this warp's two columns: 64 regs/thread.
    float4 Ea[8], Eb[8];
    {
        const float* Emat = isBeta ? g_E : g_ET;
        const float4* Ra = (const float4*)(Emat + (size_t)j0 * C);
        const float4* Rb = (const float4*)(Emat + (size_t)(j0 + 1) * C);
        #pragma unroll
        for (int u = 0; u < 8; u++) { Ea[u] = Ra[u*32 + lane]; Eb[u] = Rb[u*32 + lane]; }
    }

    float*    rowsOut = isBeta ? g_beta : out;   // centered alpha -> d_out
    double*   offArr  = isBeta ? g_offB : g_offA;

    double Cd = 0.0;
    const bool keeper = (grp == 0 && warp == 0);   // checked under lane==0

    // ---- step 0: publish q0 = exp(scores[row0]) with tag 1 into buffer 0
    float2 s_pref = make_float2(0.f, 0.f), es_pref = make_float2(0.f, 0.f);
    {
        const int row0 = isBeta ? (NSENT - 1) : 0;
        if (lane == 0) {
            float2 s0 = *(const float2*)&scores[(size_t)row0 * C + j0];
            *(float2*)&rowsOut[(size_t)row0 * C + j0] = s0;
            st_pair_rel(&g_pair[dir][0][j0],     expf(s0.x), 1u);
            st_pair_rel(&g_pair[dir][0][j0 + 1], expf(s0.y), 1u);
            const int row1 = isBeta ? (NSENT - 2) : 1;
            s_pref = *(const float2*)&scores[(size_t)row1 * C + j0];
            es_pref = make_float2(expf(s_pref.x), expf(s_pref.y));
            if (keeper) offArr[row0] = 0.0;
        }
    }

    // ---- main recurrence: 8191 dependent rounds, self-tagged strong pairs
    for (int t = 1; t < NSENT; t++) {
        const int row = isBeta ? (NSENT - 1 - t) : t;
        const int buf = (t - 1) & 1;

        float2 sv  = s_pref;
        float2 esv = es_pref;
        if (lane == 0) {
            int tn = (t + 1 < NSENT) ? (t + 1) : t;
            int rown = isBeta ? (NSENT - 1 - tn) : tn;
            s_pref = *(const float2*)&scores[(size_t)rown * C + j0];
        }

        // detect == fetch: all 256 threads poll 4 pairs each (one RT total)
        {
            const u64* base = g_pair[dir][buf] + threadIdx.x * 4;
            const unsigned want = (unsigned)t;
            u64 a, b, c0, d;
            do {
                a  = ld_pair_acq(base + 0);
                b  = ld_pair_acq(base + 1);
                c0 = ld_pair_acq(base + 2);
                d  = ld_pair_acq(base + 3);
            } while ((((unsigned)(a >> 32)) != want) | (((unsigned)(b >> 32)) != want) |
                     (((unsigned)(c0 >> 32)) != want) | (((unsigned)(d >> 32)) != want));
            float4 v;
            v.x = __uint_as_float((unsigned)a);
            v.y = __uint_as_float((unsigned)b);
            v.z = __uint_as_float((unsigned)c0);
            v.w = __uint_as_float((unsigned)d);
            ((float4*)q_sm[buf])[threadIdx.x] = v;
        }
        __syncthreads();     // the ONLY per-step CTA barrier

        // matvec for 2 columns + running max (q loaded once, used 3x)
        float aa0=0.f,aa1=0.f,aa2=0.f,aa3=0.f;
        float ab0=0.f,ab1=0.f,ab2=0.f,ab3=0.f;
        float mm0=0.f,mm1=0.f,mm2=0.f,mm3=0.f;
        const float4* p4 = (const float4*)q_sm[buf];
        #pragma unroll
        for (int u = 0; u < 8; u++) {
            float4 p = p4[u*32 + lane];
            aa0 = fmaf(p.x, Ea[u].x, aa0);  ab0 = fmaf(p.x, Eb[u].x, ab0);  mm0 = fmaxf(mm0, p.x);
            aa1 = fmaf(p.y, Ea[u].y, aa1);  ab1 = fmaf(p.y, Eb[u].y, ab1);  mm1 = fmaxf(mm1, p.y);
            aa2 = fmaf(p.z, Ea[u].z, aa2);  ab2 = fmaf(p.z, Eb[u].z, ab2);  mm2 = fmaxf(mm2, p.z);
            aa3 = fmaf(p.w, Ea[u].w, aa3);  ab3 = fmaf(p.w, Eb[u].w, ab3);  mm3 = fmaxf(mm3, p.w);
        }
        float acca = (aa0+aa1)+(aa2+aa3);
        float accb = (ab0+ab1)+(ab2+ab3);
        float mxp  = fmaxf(fmaxf(mm0,mm1), fmaxf(mm2,mm3));
        #pragma unroll
        for (int s = 16; s > 0; s >>= 1) {
            acca += __shfl_xor_sync(0xFFFFFFFFu, acca, s);
            accb += __shfl_xor_sync(0xFFFFFFFFu, accb, s);
            mxp   = fmaxf(mxp, __shfl_xor_sync(0xFFFFFFFFu, mxp, s));
        }

        if (lane == 0) {
            // ---- ON critical path: rcp + muls + two release pair stores
            float r  = frcp(mxp);             // bitwise identical in every CTA
            float qa = esv.x * acca * r;
            float qb = esv.y * accb * r;
            u64* pp = &g_pair[dir][t & 1][j0];
            st_pair_rel(pp,     qa, (unsigned)(t + 1));
            st_pair_rel(pp + 1, qb, (unsigned)(t + 1));
            // ---- OFF critical path
            float2 ah = make_float2(sv.x + logf(acca), sv.y + logf(accb));
            *(float2*)&rowsOut[(size_t)row * C + j0] = ah;
            if (keeper) {
                offArr[row] = Cd;
                Cd -= (double)logf(r);
            }
            es_pref = make_float2(expf(s_pref.x), expf(s_pref.y));
        }
    }

    // final rowsOut/offArr stores must happen-before the join release
    __syncthreads();
    if (keeper && threadIdx.x == 0 && !isBeta) g_Zbase = Cd;
    __threadfence();
    __syncthreads();

    // ---- join both directions (release/acquire flag barrier)
    if (threadIdx.x == 0) st_rel(&g_jflags[cta*FSTRIDE], 1u);
    if (threadIdx.x < NCTA_TOTAL) {
        const unsigned* fp = &g_jflags[threadIdx.x * FSTRIDE];
        while (ld_acq(fp) < 1u) { }
    }
    __syncthreads();

    // ---- Z = Zbase + log(sum q_final) (final alpha q pairs in g_pair[0][1])
    double Zd;
    {
        const u64* pz = g_pair[0][1] + threadIdx.x * 4;
        u64 a  = ld_pair_cg(pz + 0);
        u64 b  = ld_pair_cg(pz + 1);
        u64 c0 = ld_pair_cg(pz + 2);
        u64 d  = ld_pair_cg(pz + 3);
        float zs = (__uint_as_float((unsigned)a) + __uint_as_float((unsigned)b))
                 + (__uint_as_float((unsigned)c0) + __uint_as_float((unsigned)d));
        #pragma unroll
        for (int s = 16; s > 0; s >>= 1)
            zs += __shfl_xor_sync(0xFFFFFFFFu, zs, s);
        if (lane == 0) redsum[warp] = zs;
        __syncthreads();
        if (warp == 0) {
            float s = (lane < NWARP) ? redsum[lane] : 0.0f;
            #pragma unroll
            for (int sh = 4; sh > 0; sh >>= 1)
                s += __shfl_xor_sync(0xFFFFFFFFu, s, sh);
            if (lane == 0) redsum[0] = s;
        }
        __syncthreads();
        Zd = g_Zbase + (double)logf(redsum[0]);
    }

    // ---- per-row combine constants K[i] = offA[i] + offB[i] - Z
    const int rbase = cta * ROWS_PER_CTA;
    if (threadIdx.x < ROWS_PER_CTA) {
        int row = rbase + threadIdx.x;
        k_sm[threadIdx.x] = (float)(g_offA[row] + g_offB[row] - Zd);
    }
    __syncthreads();

    // ---- marginals: out = a_hat(out) + b_hat - scores + K[row]
    {
        const float4* b4 = (const float4*)g_beta;
        const float4* s4 = (const float4*)scores;
        float4* o4 = (float4*)out;
        const size_t base4 = (size_t)rbase * (C/4);
        const int    n4    = ROWS_PER_CTA * (C/4);
        for (int idx = threadIdx.x; idx < n4; idx += NTHREADS) {
            int   rl = idx >> 8;
            float K  = k_sm[rl];
            size_t i = base4 + idx;
            float4 av = __ldcg(&o4[i]);
            float4 b  = __ldcg(&b4[i]);
            float4 s  = __ldg(&s4[i]);
            float4 r;
            r.x = av.x + b.x - s.x + K;
            r.y = av.y + b.y - s.y + K;
            r.z = av.z + b.z - s.z + K;
            r.w = av.w + b.w - s.w + K;
            o4[i] = r;
        }
    }
}

extern "C" void kernel_launch(void* const* d_in, const int* in_sizes, int n_in,
                              void* d_out, int out_size) {
    const float* scores = (const float*)d_in[0];   // [8192*1024] f32
    const float* T      = (const float*)d_in[1];   // [1024*1024] f32
    float* out = (float*)d_out;                    // [8192*1024] f32

    crf_init<<<(C*C + 255) / 256, 256>>>(T);
    crf_main<<<NCTA_TOTAL, NTHREADS>>>(scores, out);
}

// round 15
// speedup vs baseline: 1.6252x; 1.6252x over previous
#include <cuda_runtime.h>
#include <math.h>

#define NSENT 8192
#define C     1024
#define NCTA  32                  // producer CTAs per direction
#define NWARP 8                   // 8 compute warps, 4 columns each
#define NTHREADS 256
#define NCTA_TOTAL (2*NCTA)       // 64
#define FSTRIDE 8
#define ROWS_PER_CTA (NSENT / NCTA_TOTAL)   // 128

// -------- device scratch (no allocations allowed) --------
__device__ __align__(16) float g_E [C*C];   // exp(T) row-major [k][j]  (beta)
__device__ __align__(16) float g_ET[C*C];   // transpose [j][k]         (alpha)
__device__ __align__(16) float g_beta[(size_t)NSENT*C];
__device__ __align__(16) float g_q[2][2][C];       // [dir][buf][class]
__device__ unsigned g_cnt[2][NCTA*FSTRIDE];        // cumulative publish counters
__device__ double   g_offA[NSENT];
__device__ double   g_offB[NSENT];
__device__ double   g_Zbase;
__device__ unsigned g_jflags[NCTA_TOTAL*FSTRIDE];

__device__ __forceinline__ unsigned ld_acq(const unsigned* p) {
    unsigned v;
    asm volatile("ld.acquire.gpu.global.u32 %0, [%1];" : "=r"(v) : "l"(p) : "memory");
    return v;
}
__device__ __forceinline__ void st_rel(unsigned* p, unsigned v) {
    asm volatile("st.release.gpu.global.u32 [%0], %1;" :: "l"(p), "r"(v) : "memory");
}
__device__ __forceinline__ void red_rel_add(unsigned* p, unsigned v) {
    asm volatile("red.release.gpu.global.add.u32 [%0], %1;" :: "l"(p), "r"(v) : "memory");
}
__device__ __forceinline__ void stv4_cg(float* p, float a, float b, float c, float d) {
    asm volatile("st.global.cg.v4.f32 [%0], {%1,%2,%3,%4};"
                 :: "l"(p), "f"(a), "f"(b), "f"(c), "f"(d) : "memory");
}
__device__ __forceinline__ float frcp(float x) {
    float r;
    asm("rcp.approx.f32 %0, %1;" : "=f"(r) : "f"(x));
    return r;
}

// -------- init kernel --------
__global__ void crf_init(const float* __restrict__ T) {
    int idx = blockIdx.x * blockDim.x + threadIdx.x;
    if (idx < C*C) {
        float e = expf(T[idx]);
        g_E[idx] = e;
        int k = idx / C, j = idx % C;
        g_ET[j*C + k] = e;
    }
    if (idx < 2*NCTA*FSTRIDE)     ((unsigned*)g_cnt)[idx] = 0u;
    if (idx < NCTA_TOTAL*FSTRIDE) g_jflags[idx] = 0u;
}

// -------- persistent forward+backward kernel --------
__global__ void __launch_bounds__(NTHREADS, 1) crf_main(const float* __restrict__ scores,
                                                        float* __restrict__ out) {
    const int  cta    = blockIdx.x;
    const bool isBeta = (cta >= NCTA);
    const int  dir    = isBeta ? 1 : 0;
    const int  grp    = isBeta ? (cta - NCTA) : cta;
    const int  warp   = threadIdx.x >> 5;
    const int  lane   = threadIdx.x & 31;
    const int  j0     = grp * 32 + warp * 4;   // 4 columns per warp

    __shared__ __align__(16) float q_sm[2][C];     // double-buffered q vector
    __shared__ float redsum[NWARP];
    __shared__ float k_sm[ROWS_PER_CTA];

    // E coefficients for this warp's four columns: 128 regs/thread.
    float4 Ea[8], Eb[8], Ec[8], Ed[8];
    {
        const float* Emat = isBeta ? g_E : g_ET;
        const float4* Ra = (const float4*)(Emat + (size_t)j0 * C);
        const float4* Rb = (const float4*)(Emat + (size_t)(j0 + 1) * C);
        const float4* Rc = (const float4*)(Emat + (size_t)(j0 + 2) * C);
        const float4* Rd = (const float4*)(Emat + (size_t)(j0 + 3) * C);
        #pragma unroll
        for (int u = 0; u < 8; u++) {
            Ea[u] = Ra[u*32 + lane]; Eb[u] = Rb[u*32 + lane];
            Ec[u] = Rc[u*32 + lane]; Ed[u] = Rd[u*32 + lane];
        }
    }

    float*    rowsOut = isBeta ? g_beta : out;   // centered alpha -> d_out
    double*   offArr  = isBeta ? g_offB : g_offA;
    unsigned* cntArr  = g_cnt[dir];

    double Cd = 0.0;
    const bool keeper = (grp == 0 && warp == 0);   // checked under lane==0

    // ---- step 0: publish q0 = exp(scores[row0]) into buffer 0, announce
    float4 s_pref = make_float4(0.f,0.f,0.f,0.f);
    float4 es_pref = make_float4(0.f,0.f,0.f,0.f);
    {
        const int row0 = isBeta ? (NSENT - 1) : 0;
        if (lane == 0) {
            float4 s0 = *(const float4*)&scores[(size_t)row0 * C + j0];
            *(float4*)&rowsOut[(size_t)row0 * C + j0] = s0;
            stv4_cg(&g_q[dir][0][j0], expf(s0.x), expf(s0.y), expf(s0.z), expf(s0.w));
            red_rel_add(&cntArr[grp*FSTRIDE], 1u);       // 8 increments/step
            const int row1 = isBeta ? (NSENT - 2) : 1;
            s_pref = *(const float4*)&scores[(size_t)row1 * C + j0];
            es_pref = make_float4(expf(s_pref.x), expf(s_pref.y),
                                  expf(s_pref.z), expf(s_pref.w));
            if (keeper) offArr[row0] = 0.0;
        }
    }

    // ---- main recurrence: 8191 dependent rounds
    for (int t = 1; t < NSENT; t++) {
        const int row = isBeta ? (NSENT - 1 - t) : t;
        const int buf = (t - 1) & 1;

        float4 sv  = s_pref;
        float4 esv = es_pref;
        if (lane == 0) {
            int tn = (t + 1 < NSENT) ? (t + 1) : t;
            int rown = isBeta ? (NSENT - 1 - tn) : tn;
            s_pref = *(const float4*)&scores[(size_t)rown * C + j0];
        }

        // detect + fetch: threads 0..31 poll one counter each, then fetch
        // that producer's 128B (32 floats) coalesced.
        if (threadIdx.x < NCTA) {
            const int g = threadIdx.x;
            const unsigned want = (unsigned)(NWARP * t);  // 8 increments/step
            while (ld_acq(&cntArr[g*FSTRIDE]) < want) { }
            const float4* src = (const float4*)(g_q[dir][buf] + g*32);
            float4 v0 = __ldcg(&src[0]);
            float4 v1 = __ldcg(&src[1]);
            float4 v2 = __ldcg(&src[2]);
            float4 v3 = __ldcg(&src[3]);
            float4 v4 = __ldcg(&src[4]);
            float4 v5 = __ldcg(&src[5]);
            float4 v6 = __ldcg(&src[6]);
            float4 v7 = __ldcg(&src[7]);
            float4* dst = (float4*)&q_sm[buf][g*32];
            dst[0] = v0; dst[1] = v1; dst[2] = v2; dst[3] = v3;
            dst[4] = v4; dst[5] = v5; dst[6] = v6; dst[7] = v7;
        }
        __syncthreads();     // the ONLY per-step CTA barrier

        // matvec for 4 columns + running max (q loaded once, used 5x)
        float aa0=0.f,aa1=0.f,aa2=0.f,aa3=0.f;
        float ab0=0.f,ab1=0.f,ab2=0.f,ab3=0.f;
        float ac0=0.f,ac1=0.f,ac2=0.f,ac3=0.f;
        float ad0=0.f,ad1=0.f,ad2=0.f,ad3=0.f;
        float mm0=0.f,mm1=0.f,mm2=0.f,mm3=0.f;
        const float4* p4 = (const float4*)q_sm[buf];
        #pragma unroll
        for (int u = 0; u < 8; u++) {
            float4 p = p4[u*32 + lane];
            aa0 = fmaf(p.x, Ea[u].x, aa0);  ab0 = fmaf(p.x, Eb[u].x, ab0);
            ac0 = fmaf(p.x, Ec[u].x, ac0);  ad0 = fmaf(p.x, Ed[u].x, ad0);
            mm0 = fmaxf(mm0, p.x);
            aa1 = fmaf(p.y, Ea[u].y, aa1);  ab1 = fmaf(p.y, Eb[u].y, ab1);
            ac1 = fmaf(p.y, Ec[u].y, ac1);  ad1 = fmaf(p.y, Ed[u].y, ad1);
            mm1 = fmaxf(mm1, p.y);
            aa2 = fmaf(p.z, Ea[u].z, aa2);  ab2 = fmaf(p.z, Eb[u].z, ab2);
            ac2 = fmaf(p.z, Ec[u].z, ac2);  ad2 = fmaf(p.z, Ed[u].z, ad2);
            mm2 = fmaxf(mm2, p.z);
            aa3 = fmaf(p.w, Ea[u].w, aa3);  ab3 = fmaf(p.w, Eb[u].w, ab3);
            ac3 = fmaf(p.w, Ec[u].w, ac3);  ad3 = fmaf(p.w, Ed[u].w, ad3);
            mm3 = fmaxf(mm3, p.w);
        }
        float acca = (aa0+aa1)+(aa2+aa3);
        float accb = (ab0+ab1)+(ab2+ab3);
        float accc = (ac0+ac1)+(ac2+ac3);
        float accd = (ad0+ad1)+(ad2+ad3);
        float mxp  = fmaxf(fmaxf(mm0,mm1), fmaxf(mm2,mm3));
        #pragma unroll
        for (int s = 16; s > 0; s >>= 1) {
            acca += __shfl_xor_sync(0xFFFFFFFFu, acca, s);
            accb += __shfl_xor_sync(0xFFFFFFFFu, accb, s);
            accc += __shfl_xor_sync(0xFFFFFFFFu, accc, s);
            accd += __shfl_xor_sync(0xFFFFFFFFu, accd, s);
            mxp   = fmaxf(mxp, __shfl_xor_sync(0xFFFFFFFFu, mxp, s));
        }

        if (lane == 0) {
            // ---- ON critical path: rcp + muls + one v4 store + one RMW
            float r  = frcp(mxp);             // bitwise identical in every CTA
            stv4_cg(&g_q[dir][t & 1][j0],
                    esv.x * acca * r, esv.y * accb * r,
                    esv.z * accc * r, esv.w * accd * r);
            red_rel_add(&cntArr[grp*FSTRIDE], 1u);
            // ---- OFF critical path
            float4 ah;
            ah.x = sv.x + logf(acca);
            ah.y = sv.y + logf(accb);
            ah.z = sv.z + logf(accc);
            ah.w = sv.w + logf(accd);
            *(float4*)&rowsOut[(size_t)row * C + j0] = ah;
            if (keeper) {
                offArr[row] = Cd;
                Cd -= (double)logf(r);
            }
            es_pref = make_float4(expf(s_pref.x), expf(s_pref.y),
                                  expf(s_pref.z), expf(s_pref.w));
        }
    }

    // final rowsOut/offArr stores must happen-before the join release
    __syncthreads();
    if (keeper && threadIdx.x == 0 && !isBeta) g_Zbase = Cd;
    __threadfence();
    __syncthreads();

    // ---- join both directions (release/acquire flag barrier)
    if (threadIdx.x == 0) st_rel(&g_jflags[cta*FSTRIDE], 1u);
    if (threadIdx.x < NCTA_TOTAL) {
        const unsigned* fp = &g_jflags[threadIdx.x * FSTRIDE];
        while (ld_acq(fp) < 1u) { }
    }
    __syncthreads();

    // ---- Z = Zbase + log(sum q_final) (final alpha q in g_q[0][1])
    double Zd;
    {
        float4 v = __ldcg(&((const float4*)g_q[0][1])[threadIdx.x]);  // 256 float4
        float zs = (v.x + v.y) + (v.z + v.w);
        #pragma unroll
        for (int s = 16; s > 0; s >>= 1)
            zs += __shfl_xor_sync(0xFFFFFFFFu, zs, s);
        if (lane == 0) redsum[warp] = zs;
        __syncthreads();
        if (warp == 0) {
            float s = (lane < NWARP) ? redsum[lane] : 0.0f;
            #pragma unroll
            for (int sh = 4; sh > 0; sh >>= 1)
                s += __shfl_xor_sync(0xFFFFFFFFu, s, sh);
            if (lane == 0) redsum[0] = s;
        }
        __syncthreads();
        Zd = g_Zbase + (double)logf(redsum[0]);
    }

    // ---- per-row combine constants K[i] = offA[i] + offB[i] - Z
    const int rbase = cta * ROWS_PER_CTA;
    for (int rr = threadIdx.x; rr < ROWS_PER_CTA; rr += NTHREADS) {
        int row = rbase + rr;
        k_sm[rr] = (float)(g_offA[row] + g_offB[row] - Zd);
    }
    __syncthreads();

    // ---- marginals: out = a_hat(out) + b_hat - scores + K[row]
    {
        const float4* b4 = (const float4*)g_beta;
        const float4* s4 = (const float4*)scores;
        float4* o4 = (float4*)out;
        const size_t base4 = (size_t)rbase * (C/4);
        const int    n4    = ROWS_PER_CTA * (C/4);
        for (int idx = threadIdx.x; idx < n4; idx += NTHREADS) {
            int   rl = idx >> 8;
            float K  = k_sm[rl];
            size_t i = base4 + idx;
            float4 av = __ldcg(&o4[i]);
            float4 b  = __ldcg(&b4[i]);
            float4 s  = __ldg(&s4[i]);
            float4 r;
            r.x = av.x + b.x - s.x + K;
            r.y = av.y + b.y - s.y + K;
            r.z = av.z + b.z - s.z + K;
            r.w = av.w + b.w - s.w + K;
            o4[i] = r;
        }
    }
}

extern "C" void kernel_launch(void* const* d_in, const int* in_sizes, int n_in,
                              void* d_out, int out_size) {
    const float* scores = (const float*)d_in[0];   // [8192*1024] f32
    const float* T      = (const float*)d_in[1];   // [1024*1024] f32
    float* out = (float*)d_out;                    // [8192*1024] f32

    crf_init<<<(C*C + 255) / 256, 256>>>(T);
    crf_main<<<NCTA_TOTAL, NTHREADS>>>(scores, out);
}

// round 17
// speedup vs baseline: 2.0513x; 1.2622x over previous
#include <cuda_runtime.h>
#include <math.h>

#define NSENT 8192
#define C     1024
#define NCTA  64                  // producer CTAs per direction
#define NWARP 8                   // 8 compute warps, 2 columns each
#define NTHREADS 256
#define NCTA_TOTAL (2*NCTA)
#define FSTRIDE 8
#define ROWS_PER_CTA (NSENT / NCTA_TOTAL)   // 64

// -------- device scratch (no allocations allowed) --------
__device__ __align__(16) float g_E [C*C];   // exp(T) row-major [k][j]  (beta)
__device__ __align__(16) float g_ET[C*C];   // transpose [j][k]         (alpha)
__device__ __align__(16) float g_beta[(size_t)NSENT*C];
__device__ __align__(16) float g_q[2][2][C];       // [dir][buf][class] UNSCALED v
// 4 counters per producer, packed 16B (coalesced polls, 2-deep RMW chains)
__device__ __align__(16) unsigned g_cnt[2][NCTA*4];
__device__ double   g_offA[NSENT];
__device__ double   g_offB[NSENT];
__device__ double   g_Zbase;               // C_{N-2} effective (pre-corrected)
__device__ unsigned g_jflags[NCTA_TOTAL*FSTRIDE];

__device__ __forceinline__ unsigned ld_acq(const unsigned* p) {
    unsigned v;
    asm volatile("ld.acquire.gpu.global.u32 %0, [%1];" : "=r"(v) : "l"(p) : "memory");
    return v;
}
__device__ __forceinline__ void st_rel(unsigned* p, unsigned v) {
    asm volatile("st.release.gpu.global.u32 [%0], %1;" :: "l"(p), "r"(v) : "memory");
}
__device__ __forceinline__ void red_rel_add(unsigned* p, unsigned v) {
    asm volatile("red.release.gpu.global.add.u32 [%0], %1;" :: "l"(p), "r"(v) : "memory");
}
__device__ __forceinline__ void stv2_cg(float* p, float a, float b) {
    asm volatile("st.global.cg.v2.f32 [%0], {%1,%2};" :: "l"(p), "f"(a), "f"(b) : "memory");
}
__device__ __forceinline__ float frcp(float x) {
    float r;
    asm("rcp.approx.f32 %0, %1;" : "=f"(r) : "f"(x));
    return r;
}

// -------- init kernel --------
__global__ void crf_init(const float* __restrict__ T) {
    int idx = blockIdx.x * blockDim.x + threadIdx.x;
    if (idx < C*C) {
        float e = expf(T[idx]);
        g_E[idx] = e;
        int k = idx / C, j = idx % C;
        g_ET[j*C + k] = e;
    }
    if (idx < 2*NCTA*4)           ((unsigned*)g_cnt)[idx] = 0u;
    if (idx < NCTA_TOTAL*FSTRIDE) g_jflags[idx] = 0u;
}

// -------- persistent forward+backward kernel --------
__global__ void __launch_bounds__(NTHREADS, 1) crf_main(const float* __restrict__ scores,
                                                        float* __restrict__ out) {
    const int  cta    = blockIdx.x;
    const bool isBeta = (cta >= NCTA);
    const int  dir    = isBeta ? 1 : 0;
    const int  grp    = isBeta ? (cta - NCTA) : cta;
    const int  warp   = threadIdx.x >> 5;
    const int  lane   = threadIdx.x & 31;
    const int  j0     = grp * 16 + warp * 2;   // 2 columns per warp

    __shared__ __align__(16) float q_sm[2][C];     // double-buffered q vector
    __shared__ float redsum[NWARP];
    __shared__ float k_sm[ROWS_PER_CTA];

    // E coefficients for this warp's two columns: 64 regs/thread.
    float4 Ea[8], Eb[8];
    {
        const float* Emat = isBeta ? g_E : g_ET;
        const float4* Ra = (const float4*)(Emat + (size_t)j0 * C);
        const float4* Rb = (const float4*)(Emat + (size_t)(j0 + 1) * C);
        #pragma unroll
        for (int u = 0; u < 8; u++) { Ea[u] = Ra[u*32 + lane]; Eb[u] = Rb[u*32 + lane]; }
    }

    float*    rowsOut = isBeta ? g_beta : out;   // centered alpha -> d_out
    double*   offArr  = isBeta ? g_offB : g_offA;
    unsigned* cntArr  = g_cnt[dir];

    double Cd = 0.0;
    const bool keeper = (grp == 0 && warp == 0);   // checked under lane==0

    // staging scale for step t's data = rcp(max q_{t-2}); 1.0 for step-0 data
    float r_stage = 1.0f;

    // ---- step 0: publish v0 = exp(scores[row0]) into buffer 0, announce
    float2 s_pref = make_float2(0.f, 0.f), es_pref = make_float2(0.f, 0.f);
    {
        const int row0 = isBeta ? (NSENT - 1) : 0;
        if (lane == 0) {
            float2 s0 = *(const float2*)&scores[(size_t)row0 * C + j0];
            *(float2*)&rowsOut[(size_t)row0 * C + j0] = s0;
            stv2_cg(&g_q[dir][0][j0], expf(s0.x), expf(s0.y));
            red_rel_add(&cntArr[grp*4 + (warp >> 1)], 1u);   // 2 incr/counter/step
            const int row1 = isBeta ? (NSENT - 2) : 1;
            s_pref = *(const float2*)&scores[(size_t)row1 * C + j0];
            es_pref = make_float2(expf(s_pref.x), expf(s_pref.y));
            if (keeper) offArr[row0] = 0.0;
        }
    }

    // ---- main recurrence: 8191 dependent rounds
    for (int t = 1; t < NSENT; t++) {
        const int row = isBeta ? (NSENT - 1 - t) : t;
        const int buf = (t - 1) & 1;

        float2 sv  = s_pref;
        float2 esv = es_pref;
        if (lane == 0) {
            int tn = (t + 1 < NSENT) ? (t + 1) : t;
            int rown = isBeta ? (NSENT - 1 - tn) : tn;
            s_pref = *(const float2*)&scores[(size_t)rown * C + j0];
        }

        // detect + fetch + scale: ALL 256 threads; thread g handles producer
        // g>>2, quadrant g&3 (16B). Counter chains are only 2-deep.
        {
            const int p = threadIdx.x >> 2;
            const int c = threadIdx.x & 3;
            const unsigned want = 2u * (unsigned)t;
            while (ld_acq(&cntArr[p*4 + c]) < want) { }
            float4 v = __ldcg((const float4*)(g_q[dir][buf] + p*16 + c*4));
            float4 q;
            q.x = v.x * r_stage;  q.y = v.y * r_stage;
            q.z = v.z * r_stage;  q.w = v.w * r_stage;
            ((float4*)q_sm[buf])[threadIdx.x] = q;
        }
        __syncthreads();     // the ONLY per-step CTA barrier

        // matvec for 2 columns + running max (q loaded once, used 3x)
        float aa0=0.f,aa1=0.f,aa2=0.f,aa3=0.f;
        float ab0=0.f,ab1=0.f,ab2=0.f,ab3=0.f;
        float mm0=0.f,mm1=0.f,mm2=0.f,mm3=0.f;
        const float4* p4 = (const float4*)q_sm[buf];
        #pragma unroll
        for (int u = 0; u < 8; u++) {
            float4 p = p4[u*32 + lane];
            aa0 = fmaf(p.x, Ea[u].x, aa0);  ab0 = fmaf(p.x, Eb[u].x, ab0);  mm0 = fmaxf(mm0, p.x);
            aa1 = fmaf(p.y, Ea[u].y, aa1);  ab1 = fmaf(p.y, Eb[u].y, ab1);  mm1 = fmaxf(mm1, p.y);
            aa2 = fmaf(p.z, Ea[u].z, aa2);  ab2 = fmaf(p.z, Eb[u].z, ab2);  mm2 = fmaxf(mm2, p.z);
            aa3 = fmaf(p.w, Ea[u].w, aa3);  ab3 = fmaf(p.w, Eb[u].w, ab3);  mm3 = fmaxf(mm3, p.w);
        }
        float acca = (aa0+aa1)+(aa2+aa3);
        float accb = (ab0+ab1)+(ab2+ab3);
        float mxp  = fmaxf(fmaxf(mm0,mm1), fmaxf(mm2,mm3));

        // acc reduce FIRST: publish depends only on acc
        #pragma unroll
        for (int s = 16; s > 0; s >>= 1) {
            acca += __shfl_xor_sync(0xFFFFFFFFu, acca, s);
            accb += __shfl_xor_sync(0xFFFFFFFFu, accb, s);
        }
        if (lane == 0) {
            // ---- ON critical path: 2 muls + one v2 store + one 2-deep RMW
            stv2_cg(&g_q[dir][t & 1][j0], esv.x * acca, esv.y * accb);
            red_rel_add(&cntArr[grp*4 + (warp >> 1)], 1u);
        }
        // mxp reduce AFTER publish (feeds next step's staging scale)
        #pragma unroll
        for (int s = 16; s > 0; s >>= 1)
            mxp = fmaxf(mxp, __shfl_xor_sync(0xFFFFFFFFu, mxp, s));
        float rnew = frcp(mxp);               // bitwise identical in every CTA

        if (lane == 0) {
            // ---- OFF critical path
            float2 ah = make_float2(sv.x + logf(acca), sv.y + logf(accb));
            *(float2*)&rowsOut[(size_t)row * C + j0] = ah;
            if (keeper) {
                offArr[row] = Cd;
                Cd -= (double)logf(rnew);
            }
            es_pref = make_float2(expf(s_pref.x), expf(s_pref.y));
        }
        r_stage = rnew;
    }

    // final rowsOut/offArr stores must happen-before the join release
    __syncthreads();
    // stored finals are UNSCALED v: Zbase = C_{8190} = Cd + log(r_last)
    if (keeper && threadIdx.x == 0 && !isBeta)
        g_Zbase = Cd + (double)logf(r_stage);
    __threadfence();
    __syncthreads();

    // ---- join both directions (release/acquire flag barrier)
    if (threadIdx.x == 0) st_rel(&g_jflags[cta*FSTRIDE], 1u);
    if (threadIdx.x < NCTA_TOTAL) {
        const unsigned* fp = &g_jflags[threadIdx.x * FSTRIDE];
        while (ld_acq(fp) < 1u) { }
    }
    __syncthreads();

    // ---- Z = Zbase + log(sum v_final) (final alpha v in g_q[0][1])
    double Zd;
    {
        float4 v = __ldcg(&((const float4*)g_q[0][1])[threadIdx.x]);  // 256 float4
        float zs = (v.x + v.y) + (v.z + v.w);
        #pragma unroll
        for (int s = 16; s > 0; s >>= 1)
            zs += __shfl_xor_sync(0xFFFFFFFFu, zs, s);
        if (lane == 0) redsum[warp] = zs;
        __syncthreads();
        if (warp == 0) {
            float s = (lane < NWARP) ? redsum[lane] : 0.0f;
            #pragma unroll
            for (int sh = 4; sh > 0; sh >>= 1)
                s += __shfl_xor_sync(0xFFFFFFFFu, s, sh);
            if (lane == 0) redsum[0] = s;
        }
        __syncthreads();
        Zd = g_Zbase + (double)logf(redsum[0]);
    }

    // ---- per-row combine constants K[i] = offA[i] + offB[i] - Z
    const int rbase = cta * ROWS_PER_CTA;
    if (threadIdx.x < ROWS_PER_CTA) {
        int row = rbase + threadIdx.x;
        k_sm[threadIdx.x] = (float)(g_offA[row] + g_offB[row] - Zd);
    }
    __syncthreads();

    // ---- marginals: out = a_hat(out) + b_hat - scores + K[row]
    {
        const float4* b4 = (const float4*)g_beta;
        const float4* s4 = (const float4*)scores;
        float4* o4 = (float4*)out;
        const size_t base4 = (size_t)rbase * (C/4);
        const int    n4    = ROWS_PER_CTA * (C/4);
        for (int idx = threadIdx.x; idx < n4; idx += NTHREADS) {
            int   rl = idx >> 8;
            float K  = k_sm[rl];
            size_t i = base4 + idx;
            float4 av = __ldcg(&o4[i]);
            float4 b  = __ldcg(&b4[i]);
            float4 s  = __ldg(&s4[i]);
            float4 r;
            r.x = av.x + b.x - s.x + K;
            r.y = av.y + b.y - s.y + K;
            r.z = av.z + b.z - s.z + K;
            r.w = av.w + b.w - s.w + K;
            o4[i] = r;
        }
    }
}

extern "C" void kernel_launch(void* const* d_in, const int* in_sizes, int n_in,
                              void* d_out, int out_size) {
    const float* scores = (const float*)d_in[0];   // [8192*1024] f32
    const float* T      = (const float*)d_in[1];   // [1024*1024] f32
    float* out = (float*)d_out;                    // [8192*1024] f32

    crf_init<<<(C*C + 255) / 256, 256>>>(T);
    crf_main<<<NCTA_TOTAL, NTHREADS>>>(scores, out);
}